// round 6
// baseline (speedup 1.0000x reference)
#include <cuda_runtime.h>

// DeformConv3d, dimension='HW': t-offset == 0 -> pure 2D bilinear at integer t.
// R6 = R5 (c4 channels-last gathers, G=4 weight-LDS amortization, kt 3-split)
//  + software-pipelined temp offset loads (hide L2/DRAM latency of temp)
//  + lane remap: warp = 32 consecutive w of one h-row, j = 4 h-rows
//    (coalesced offset loads + stores, longer w-runs per gather wavefront)

#define NB  2
#define NC  16
#define NT  8
#define NH  64
#define NW  64
#define NCO 16
#define NK  27
#define HW  (NH * NW)     // 4096
#define THW (NT * HW)     // 32768

#define FMA2(d, a, b) \
    asm("fma.rn.f32x2 %0, %1, %2, %0;" : "+l"(d) : "l"(a), "l"(b))
#define PACK2(d, lo, hi) \
    asm("mov.b64 %0, {%1, %2};" : "=l"(d) : "f"(lo), "f"(hi))
#define PACKB(d, s) \
    asm("mov.b64 %0, {%1, %1};" : "=l"(d) : "f"(s))
#define UNPACK2(lo, hi, s) \
    asm("mov.b64 {%0, %1}, %2;" : "=f"(lo), "=f"(hi) : "l"(s))

// x in c4-grouped channels-last layout: [b][t][g][hw] of float4 (c = 4g+j)
__device__ __align__(16) float g_x4[NB * NT * 4 * HW * 4];

__global__ void transpose_x_kernel(const float* __restrict__ x)
{
    const int tid = blockIdx.x * blockDim.x + threadIdx.x;  // 0 .. 262143
    const int hw = tid & (HW - 1);
    const int g  = (tid >> 12) & 3;
    const int t  = (tid >> 14) & 7;
    const int b  = tid >> 17;
    float4 v;
    v.x = x[((b * NC + 4 * g + 0) * NT + t) * HW + hw];
    v.y = x[((b * NC + 4 * g + 1) * NT + t) * HW + hw];
    v.z = x[((b * NC + 4 * g + 2) * NT + t) * HW + hw];
    v.w = x[((b * NC + 4 * g + 3) * NT + t) * HW + hw];
    reinterpret_cast<float4*>(g_x4)[tid] = v;
}

// ---------------------------------------------------------------------------
// Block = 192 threads = 3 kt-parts x 64 lanes. lane = w (0..63, i.e. one full
// w-row per 2 warps); thread computes points (h0+j, w), j = 0..3.
// Block covers (b, t, 4 h-rows) = 256 output points. Grid = 256 blocks.
#define TPB 192

__global__ void __launch_bounds__(TPB, 2)
deform_conv3d_hw_kernel(const float* __restrict__ temp,
                        const float* __restrict__ wgt,
                        const float* __restrict__ bias,
                        float* __restrict__ out)
{
    // weights as [k][c][co]: 16 contiguous co per (k,c) -> LDS.128 broadcast
    __shared__ __align__(16) float wsm[NK * NC * NCO];                // 27648 B
    __shared__ __align__(16) unsigned long long redsm[2][64][2][8];   // 16384 B

    for (int i = threadIdx.x; i < NK * NC * NCO; i += TPB) {
        int co = i & 15;
        int c  = (i >> 4) & 15;
        int k  = i >> 8;
        wsm[i] = wgt[(co * NC + c) * NK + k];
    }

    const int part = threadIdx.x / 64;          // warp-coherent
    const int w    = threadIdx.x & 63;          // lane = w
    const int bid  = blockIdx.x;                // b*128 + t*16 + hgrp
    const int hb = (bid & 15) << 2;             // base of 4 h-rows
    const int t  = (bid >> 4) & 7;
    const int b  = bid >> 7;

    unsigned long long acc[4][8];
    if (part == 0) {
#pragma unroll
        for (int j = 0; j < 4; j++)
#pragma unroll
            for (int m = 0; m < 8; m++)
                PACK2(acc[j][m], bias[2 * m], bias[2 * m + 1]);
    } else {
#pragma unroll
        for (int j = 0; j < 4; j++)
#pragma unroll
            for (int m = 0; m < 8; m++) acc[j][m] = 0ULL;
    }

    const int ti = t - 1 + part;
    const bool active = (ti >= 0) && (ti < NT);

    // temp base for this part's tap block; per (k, j): + (2k)*THW + j*NW
    const float* __restrict__ tb =
        temp + b * (2 * NK * THW) + t * HW + hb * NW + w;
    const int kbase = part * 9;

    // prefetch tap 0 offsets (before the sync so they overlap the wsm fill)
    float noh[4], now_[4];
    if (active) {
#pragma unroll
        for (int j = 0; j < 4; j++) {
            noh[j]  = __ldg(tb + (2 * kbase) * THW + j * NW);
            now_[j] = __ldg(tb + (2 * kbase + 1) * THW + j * NW);
        }
    }

    __syncthreads();   // wsm ready

    if (active) {
        const ulonglong2* __restrict__ x4base =
            reinterpret_cast<const ulonglong2*>(g_x4) + (b * NT + ti) * 4 * HW;

#pragma unroll
        for (int kk = 0; kk < 9; kk++) {
            const int kh = kk / 3;
            const int kw = kk - kh * 3;
            const int k  = kbase + kk;

            // consume prefetched offsets; issue next tap's loads immediately
            float offh[4], offw[4];
#pragma unroll
            for (int j = 0; j < 4; j++) { offh[j] = noh[j]; offw[j] = now_[j]; }
            if (kk < 8) {
#pragma unroll
                for (int j = 0; j < 4; j++) {
                    noh[j]  = __ldg(tb + (2 * (k + 1)) * THW + j * NW);
                    now_[j] = __ldg(tb + (2 * (k + 1) + 1) * THW + j * NW);
                }
            }

            float ccf[4][4];
            int   idx[4][4];
#pragma unroll
            for (int j = 0; j < 4; j++) {
                const int h = hb + j;

                const float ph = (float)(h - 1 + kh) + offh[j];
                const float pw = (float)(w - 1 + kw) + offw[j];

                const int h0 = __float2int_rd(ph);
                const int w0 = __float2int_rd(pw);
                const float fh = ph - (float)h0;
                const float fw = pw - (float)w0;
                const int h1 = h0 + 1;
                const int w1 = w0 + 1;

                const bool vh0 = (h0 >= 0) & (h0 < NH);
                const bool vh1 = (h1 >= 0) & (h1 < NH);
                const bool vw0 = (w0 >= 0) & (w0 < NW);
                const bool vw1 = (w1 >= 0) & (w1 < NW);

                const float gh0 = 1.0f - fh, gw0 = 1.0f - fw;
                ccf[j][0] = (vh0 & vw0) ? gh0 * gw0 : 0.0f;
                ccf[j][1] = (vh0 & vw1) ? gh0 * fw  : 0.0f;
                ccf[j][2] = (vh1 & vw0) ? fh  * gw0 : 0.0f;
                ccf[j][3] = (vh1 & vw1) ? fh  * fw  : 0.0f;

                const int h0c = min(max(h0, 0), NH - 1);
                const int h1c = min(max(h1, 0), NH - 1);
                const int w0c = min(max(w0, 0), NW - 1);
                const int w1c = min(max(w1, 0), NW - 1);
                idx[j][0] = h0c * NW + w0c;
                idx[j][1] = h0c * NW + w1c;
                idx[j][2] = h1c * NW + w0c;
                idx[j][3] = h1c * NW + w1c;
            }

#pragma unroll
            for (int g = 0; g < 4; g++) {
                const ulonglong2* __restrict__ pg = x4base + g * HW;

                // bilinear values for 4 points: u[j] packs channels
                // {4g,4g+1} (lo) and {4g+2,4g+3} (hi)
                unsigned long long u[4][2];
#pragma unroll
                for (int j = 0; j < 4; j++) {
                    u[j][0] = 0ULL; u[j][1] = 0ULL;
#pragma unroll
                    for (int q = 0; q < 4; q++) {
                        unsigned long long cc;
                        PACKB(cc, ccf[j][q]);
                        const ulonglong2 a = __ldg(pg + idx[j][q]);
                        FMA2(u[j][0], cc, a.x);
                        FMA2(u[j][1], cc, a.y);
                    }
                }

                // GEMM: weights for channels 4g..4g+3, loaded once, used 4x
                const ulonglong2* __restrict__ wr =
                    (const ulonglong2*)(wsm + (k * NC + 4 * g) * NCO);
#pragma unroll
                for (int cp = 0; cp < 2; cp++) {
                    const ulonglong2 q0 = wr[cp * 8 + 0];
                    const ulonglong2 q1 = wr[cp * 8 + 1];
                    const ulonglong2 q2 = wr[cp * 8 + 2];
                    const ulonglong2 q3 = wr[cp * 8 + 3];
                    const ulonglong2 r0 = wr[cp * 8 + 4];
                    const ulonglong2 r1 = wr[cp * 8 + 5];
                    const ulonglong2 r2 = wr[cp * 8 + 6];
                    const ulonglong2 r3 = wr[cp * 8 + 7];
#pragma unroll
                    for (int j = 0; j < 4; j++) {
                        float v0, v1;
                        UNPACK2(v0, v1, u[j][cp]);
                        unsigned long long vv0, vv1;
                        PACKB(vv0, v0);
                        PACKB(vv1, v1);
                        FMA2(acc[j][0], vv0, q0.x); FMA2(acc[j][1], vv0, q0.y);
                        FMA2(acc[j][2], vv0, q1.x); FMA2(acc[j][3], vv0, q1.y);
                        FMA2(acc[j][4], vv0, q2.x); FMA2(acc[j][5], vv0, q2.y);
                        FMA2(acc[j][6], vv0, q3.x); FMA2(acc[j][7], vv0, q3.y);
                        FMA2(acc[j][0], vv1, r0.x); FMA2(acc[j][1], vv1, r0.y);
                        FMA2(acc[j][2], vv1, r1.x); FMA2(acc[j][3], vv1, r1.y);
                        FMA2(acc[j][4], vv1, r2.x); FMA2(acc[j][5], vv1, r2.y);
                        FMA2(acc[j][6], vv1, r3.x); FMA2(acc[j][7], vv1, r3.y);
                    }
                }
            }
        }
    }

    // reduce parts 1,2 into part 0 through smem, two j-waves to bound smem
#pragma unroll
    for (int wave = 0; wave < 2; wave++) {
        if (part > 0) {
#pragma unroll
            for (int jj = 0; jj < 2; jj++)
#pragma unroll
                for (int m = 0; m < 8; m++)
                    redsm[part - 1][w][jj][m] = acc[2 * wave + jj][m];
        }
        __syncthreads();
        if (part == 0) {
#pragma unroll
            for (int jj = 0; jj < 2; jj++) {
                const int j = 2 * wave + jj;
                float* ob = out + b * (NCO * THW) + t * HW
                            + (hb + j) * NW + w;
#pragma unroll
                for (int m = 0; m < 8; m++) {
                    float a0, a1, p0, p1, q0, q1;
                    UNPACK2(a0, a1, acc[j][m]);
                    UNPACK2(p0, p1, redsm[0][w][jj][m]);
                    UNPACK2(q0, q1, redsm[1][w][jj][m]);
                    ob[(2 * m) * THW]     = a0 + p0 + q0;
                    ob[(2 * m + 1) * THW] = a1 + p1 + q1;
                }
            }
        }
        __syncthreads();
    }
}

extern "C" void kernel_launch(void* const* d_in, const int* in_sizes, int n_in,
                              void* d_out, int out_size)
{
    const float* x    = (const float*)d_in[0];
    const float* temp = (const float*)d_in[1];
    const float* wgt  = (const float*)d_in[2];
    const float* bias = (const float*)d_in[3];
    float* out = (float*)d_out;

    transpose_x_kernel<<<(NB * NT * 4 * HW) / 256, 256>>>(x);

    deform_conv3d_hw_kernel<<<256, TPB>>>(temp, wgt, bias, out);
}